// round 15
// baseline (speedup 1.0000x reference)
#include <cuda_runtime.h>
#include <cuda_bf16.h>

// ManifoldConstrainedHyperConnection — R12 envelope (512 thr, float4 slices,
// G=4, same-iteration F, hoisted worker F-loads, L2 prefetch, single-slot
// smem) + R14's good deltas only:
//   - warps 2-15: pure workers (arrive barA, hoist xf, prefetch, sync barB, F)
//   - warps 0-1:  sync barA, per-warp reduce of OWN 2 tokens' 48 values
//                 (__syncwarp only), scalar sinkhorn, write own sM share,
//                 sync barB, prefetch, F with post-barB loads (no reg poison)
// barA: id1 count512 (448 arrive + 64 sync). barB: id2 count512 (all sync).

#define WRK 24
#define DDIM 2048
#define WS 4
#define THREADS 512
#define NW 16
#define G 4
#define EPSV 1e-6f

#define SMEM_WR (WRK * DDIM)            // 49152 floats (192 KB)
#define SP_STRIDE 100
#define SMEM_SP (NW * SP_STRIDE)        // 1600 floats
#define SMEM_FLOATS (SMEM_WR + SMEM_SP + 96 + 64)
#define SMEM_BYTES (SMEM_FLOATS * 4)

#define FULLM 0xffffffffu

#define BAR_ARRIVE(id, n)  asm volatile("bar.arrive %0, %1;" :: "r"(id), "r"(n) : "memory")
#define BAR_SYNC(id, n)    asm volatile("bar.sync %0, %1;"   :: "r"(id), "r"(n) : "memory")

__device__ __forceinline__ float4 ld_cg4(const float* p) {
    return __ldcg(reinterpret_cast<const float4*>(p));
}

// butterfly step: values r[0..n-1] -> r[0..n/2-1]
#define BFLY_STEP(r, n, o)                                              \
    {                                                                   \
        const bool hi_ = (lane & (o)) != 0;                             \
        _Pragma("unroll")                                               \
        for (int v_ = 0; v_ < (n) / 2; v_++) {                          \
            float mine_  = hi_ ? r[v_ + (n) / 2] : r[v_];               \
            float other_ = hi_ ? r[v_] : r[v_ + (n) / 2];               \
            r[v_] = mine_ + __shfl_xor_sync(FULLM, other_, (o));        \
        }                                                               \
    }

__global__ void __launch_bounds__(THREADS, 1)
mchc_kernel(const float* __restrict__ x, const float* __restrict__ Wr,
            const float* __restrict__ br, float* __restrict__ out, int ntok)
{
    extern __shared__ float sm[];
    float* sWr  = sm;
    float* sP   = sm + SMEM_WR;
    float* sRaw = sP + SMEM_SP;      // 96 floats, raw index v = 4k + t
    float* sM   = sRaw + 96;         // 64 floats: sM[t*16 + i*4 + j]

    const int tid  = threadIdx.x;
    const int lane = tid & 31;
    const int warp = tid >> 5;
    const int d0   = tid * 4;

    // stage W_router into smem once
    for (int i = tid * 4; i < SMEM_WR; i += THREADS * 4)
        *reinterpret_cast<float4*>(sWr + i) = *reinterpret_cast<const float4*>(Wr + i);
    __syncthreads();

    const int ngroups = (ntok + G - 1) / G;

    for (int g = blockIdx.x; g < ngroups; g += gridDim.x) {
        const int n0 = g * G;

        // ---- A: pass-1 read (L2-warm from prefetch) -> stream means ----
        float4 mx[G];
        #pragma unroll
        for (int t = 0; t < G; t++) {
            mx[t] = make_float4(0.f, 0.f, 0.f, 0.f);
            if (n0 + t < ntok) {
                const float* p = x + (size_t)(n0 + t) * (WS * DDIM) + d0;
                #pragma unroll
                for (int w = 0; w < WS; w++) {
                    float4 v = ld_cg4(p + w * DDIM);
                    mx[t].x += v.x; mx[t].y += v.y; mx[t].z += v.z; mx[t].w += v.w;
                }
                mx[t].x *= 0.25f; mx[t].y *= 0.25f; mx[t].z *= 0.25f; mx[t].w *= 0.25f;
            }
        }

        // ---- B: router partials, 3 sets of 32 values (v = 4k + t) ----
        float res0, res1, res2;
        #pragma unroll
        for (int set = 0; set < 3; set++) {
            float a[32];
            #pragma unroll
            for (int kk = 0; kk < 8; kk++) {
                const int k = 8 * set + kk;
                float4 wv = *reinterpret_cast<const float4*>(sWr + k * DDIM + d0);
                #pragma unroll
                for (int t = 0; t < G; t++)
                    a[kk * 4 + t] = wv.x * mx[t].x + wv.y * mx[t].y +
                                    wv.z * mx[t].z + wv.w * mx[t].w;
            }
            BFLY_STEP(a, 32, 16)
            BFLY_STEP(a, 16, 8)
            BFLY_STEP(a, 8, 4)
            BFLY_STEP(a, 4, 2)
            BFLY_STEP(a, 2, 1)
            if (set == 0) res0 = a[0];
            else if (set == 1) res1 = a[0];
            else res2 = a[0];
        }
        sP[warp * SP_STRIDE + lane]      = res0;
        sP[warp * SP_STRIDE + 32 + lane] = res1;
        sP[warp * SP_STRIDE + 64 + lane] = res2;

        if (warp >= 2) {
            // ============ WORKER (warps 2-15) ============
            BAR_ARRIVE(1, THREADS);                 // publish sP, non-blocking

            // hoist F-phase loads first (critical path to F; L2 hits)
            float4 xf[G][WS];
            #pragma unroll
            for (int t = 0; t < G; t++) {
                const float* p = x + (size_t)(n0 + t) * (WS * DDIM) + d0;
                const bool ok = (n0 + t) < ntok;
                #pragma unroll
                for (int w = 0; w < WS; w++)
                    xf[t][w] = ok ? ld_cg4(p + w * DDIM) : make_float4(0,0,0,0);
            }

            // warm next group's x into L2 (off critical path)
            const int gn = g + gridDim.x;
            if (gn < ngroups) {
                const char* pb = reinterpret_cast<const char*>(
                                     x + (size_t)gn * G * (WS * DDIM)) + tid * 256;
                asm volatile("prefetch.global.L2 [%0];" :: "l"(pb));
                asm volatile("prefetch.global.L2 [%0];" :: "l"(pb + 128));
            }

            BAR_SYNC(2, THREADS);                   // wait for M (hidden by loads)

            #pragma unroll
            for (int t = 0; t < G; t++) {
                if (n0 + t < ntok) {
                    float* o = out + (size_t)(n0 + t) * (WS * DDIM) + d0;
                    #pragma unroll
                    for (int i = 0; i < WS; i++) {
                        float4 Mi = *reinterpret_cast<const float4*>(sM + t * 16 + i * 4);
                        float4 ov;
                        ov.x = Mi.x*xf[t][0].x + Mi.y*xf[t][1].x + Mi.z*xf[t][2].x + Mi.w*xf[t][3].x;
                        ov.y = Mi.x*xf[t][0].y + Mi.y*xf[t][1].y + Mi.z*xf[t][2].y + Mi.w*xf[t][3].y;
                        ov.z = Mi.x*xf[t][0].z + Mi.y*xf[t][1].z + Mi.z*xf[t][2].z + Mi.w*xf[t][3].z;
                        ov.w = Mi.x*xf[t][0].w + Mi.y*xf[t][1].w + Mi.z*xf[t][2].w + Mi.w*xf[t][3].w;
                        __stcs(reinterpret_cast<float4*>(o + i * DDIM), ov);
                    }
                }
            }
        } else {
            // ============ ROUTER (warps 0-1) ============
            BAR_SYNC(1, THREADS);                   // barA: sP complete

            // reduce ONLY this warp's 2 tokens' values (t parity = lane&1)
            // pass 1: k = lane>>1 (0..15), t = 2*warp + (lane&1)
            {
                const int k = lane >> 1;
                const int t = 2 * warp + (lane & 1);
                const int v = 4 * k + t;
                float acc = __ldg(br + k);
                #pragma unroll
                for (int w = 0; w < NW; w++)
                    acc += sP[w * SP_STRIDE + v];
                sRaw[v] = acc;
            }
            // pass 2: k = 16 + (lane>>1) for lane < 16
            if (lane < 16) {
                const int k = 16 + (lane >> 1);
                const int t = 2 * warp + (lane & 1);
                const int v = 4 * k + t;
                float acc = __ldg(br + k);
                #pragma unroll
                for (int w = 0; w < NW; w++)
                    acc += sP[w * SP_STRIDE + v];
                sRaw[v] = acc;
            }
            __syncwarp();                           // sRaw visible within warp

            // scalar softmax + sinkhorn; token t = 2*warp + (lane>>4)
            {
                const int t = 2 * warp + (lane >> 4);

                float p0 = sRaw[0*4+t], p1 = sRaw[1*4+t], p2 = sRaw[2*4+t], p3 = sRaw[3*4+t];
                float mp = fmaxf(fmaxf(p0, p1), fmaxf(p2, p3));
                p0 = __expf(p0 - mp); p1 = __expf(p1 - mp);
                p2 = __expf(p2 - mp); p3 = __expf(p3 - mp);
                float isp = __fdividef(1.f, p0 + p1 + p2 + p3);
                p0 *= isp; p1 *= isp; p2 *= isp; p3 *= isp;

                float q0 = sRaw[4*4+t], q1 = sRaw[5*4+t], q2 = sRaw[6*4+t], q3 = sRaw[7*4+t];
                float mq = fmaxf(fmaxf(q0, q1), fmaxf(q2, q3));
                q0 = __expf(q0 - mq); q1 = __expf(q1 - mq);
                q2 = __expf(q2 - mq); q3 = __expf(q3 - mq);
                float isq = __fdividef(1.f, q0 + q1 + q2 + q3);
                q0 *= isq; q1 *= isq; q2 *= isq; q3 *= isq;

                float av[16];
                #pragma unroll
                for (int i = 0; i < 4; i++)
                    #pragma unroll
                    for (int j = 0; j < 4; j++)
                        av[i*4+j] = __expf(sRaw[(8 + i*4 + j)*4 + t] + (i == j ? 2.0f : -2.0f));

                #pragma unroll
                for (int itn = 0; itn < 4; itn++) {
                    #pragma unroll
                    for (int i = 0; i < 4; i++) {
                        float rs  = av[i*4] + av[i*4+1] + av[i*4+2] + av[i*4+3];
                        float inv = __fdividef(1.f, fmaxf(rs, EPSV));
                        av[i*4] *= inv; av[i*4+1] *= inv; av[i*4+2] *= inv; av[i*4+3] *= inv;
                    }
                    #pragma unroll
                    for (int j = 0; j < 4; j++) {
                        float cs  = av[j] + av[4+j] + av[8+j] + av[12+j];
                        float inv = __fdividef(1.f, fmaxf(cs, EPSV));
                        av[j] *= inv; av[4+j] *= inv; av[8+j] *= inv; av[12+j] *= inv;
                    }
                }

                if ((lane & 15) == 0) {
                    const float pre[4]  = {p0, p1, p2, p3};
                    const float post[4] = {q0, q1, q2, q3};
                    #pragma unroll
                    for (int i = 0; i < 4; i++) {
                        float4 mrow;
                        mrow.x = av[i*4+0] + post[i] * pre[0];
                        mrow.y = av[i*4+1] + post[i] * pre[1];
                        mrow.z = av[i*4+2] + post[i] * pre[2];
                        mrow.w = av[i*4+3] + post[i] * pre[3];
                        *reinterpret_cast<float4*>(sM + t * 16 + i * 4) = mrow;
                    }
                }
            }
            BAR_SYNC(2, THREADS);                   // barB: releases workers,
                                                    // drains sM stores

            // prefetch share (warps 0-1)
            const int gn = g + gridDim.x;
            if (gn < ngroups) {
                const char* pb = reinterpret_cast<const char*>(
                                     x + (size_t)gn * G * (WS * DDIM)) + tid * 256;
                asm volatile("prefetch.global.L2 [%0];" :: "l"(pb));
                asm volatile("prefetch.global.L2 [%0];" :: "l"(pb + 128));
            }

            // F with fresh loads (L2 hits; only 2 of 16 warps take this path)
            #pragma unroll
            for (int t = 0; t < G; t++) {
                if (n0 + t < ntok) {
                    const float* p = x + (size_t)(n0 + t) * (WS * DDIM) + d0;
                    float*       o = out + (size_t)(n0 + t) * (WS * DDIM) + d0;
                    float4 x0 = ld_cg4(p);
                    float4 x1 = ld_cg4(p + DDIM);
                    float4 x2 = ld_cg4(p + 2 * DDIM);
                    float4 x3 = ld_cg4(p + 3 * DDIM);
                    #pragma unroll
                    for (int i = 0; i < WS; i++) {
                        float4 Mi = *reinterpret_cast<const float4*>(sM + t * 16 + i * 4);
                        float4 ov;
                        ov.x = Mi.x*x0.x + Mi.y*x1.x + Mi.z*x2.x + Mi.w*x3.x;
                        ov.y = Mi.x*x0.y + Mi.y*x1.y + Mi.z*x2.y + Mi.w*x3.y;
                        ov.z = Mi.x*x0.z + Mi.y*x1.z + Mi.z*x2.z + Mi.w*x3.z;
                        ov.w = Mi.x*x0.w + Mi.y*x1.w + Mi.z*x2.w + Mi.w*x3.w;
                        __stcs(reinterpret_cast<float4*>(o + i * DDIM), ov);
                    }
                }
            }
        }
        // single-slot reuse ordering:
        //   sP(it+1): written only after barB(it) sync (program order)       ✓
        //   sM(it+1): routers write only after barA(it+1), which requires all
        //             workers arrived, i.e. finished F(it) reads of sM       ✓
        //   sRaw(it+1): router-private between barA and barB                 ✓
    }
}

extern "C" void kernel_launch(void* const* d_in, const int* in_sizes, int n_in,
                              void* d_out, int out_size)
{
    const float* x  = (const float*)d_in[0];
    const float* Wr = (const float*)d_in[1];
    const float* br = (const float*)d_in[2];
    float* out = (float*)d_out;

    int ntok = in_sizes[0] / (WS * DDIM);   // 8192

    cudaFuncSetAttribute(mchc_kernel,
                         cudaFuncAttributeMaxDynamicSharedMemorySize, SMEM_BYTES);

    int sms = 148, dev = 0;
    if (cudaGetDevice(&dev) == cudaSuccess) {
        int v = 0;
        if (cudaDeviceGetAttribute(&v, cudaDevAttrMultiProcessorCount, dev) == cudaSuccess && v > 0)
            sms = v;
    }
    int ngroups = (ntok + G - 1) / G;
    int grid = (ngroups < sms) ? ngroups : sms;

    mchc_kernel<<<grid, THREADS, SMEM_BYTES>>>(x, Wr, br, out, ntok);
}

// round 16
// speedup vs baseline: 1.4627x; 1.4627x over previous
#include <cuda_runtime.h>
#include <cuda_bf16.h>

// ManifoldConstrainedHyperConnection — R12 (best: 121.3us) with dynamic work
// stealing. Bodies of the worker/router divergent region are byte-identical
// to R12 to preserve the known-good register allocation; the only additions:
//   - __device__ global group counter, reset by a tiny pre-kernel each launch
//   - warp 2 lane 0 grabs the CTA's group-after-next (atomicAdd) right after
//     its barA sync and publishes it in smem (ordered by bar3/barB)
//   - loop carries (g, gn1): gn1 was grabbed last iteration, so the L2
//     prefetch keeps its full one-group lead time
// This removes the 13-vs-14-groups tail quantization (2048 groups / 152 CTAs)
// and equalizes per-CTA speed spread.

#define WRK 24
#define DDIM 2048
#define WS 4
#define THREADS 512
#define NW 16
#define G 4
#define EPSV 1e-6f

#define SMEM_WR (WRK * DDIM)            // 49152 floats (192 KB)
#define SP_STRIDE 100
#define SMEM_SP (NW * SP_STRIDE)        // 1600 floats
#define SMEM_FLOATS (SMEM_WR + SMEM_SP + 96 + 64 + 4)
#define SMEM_BYTES (SMEM_FLOATS * 4)

#define FULLM 0xffffffffu

// barriers: 1 = barA (512), 2 = barB (512), 3 = reduce-done (96), 4 = M-vis (64)
#define BAR_ARRIVE(id, n)  asm volatile("bar.arrive %0, %1;" :: "r"(id), "r"(n) : "memory")
#define BAR_SYNC(id, n)    asm volatile("bar.sync %0, %1;"   :: "r"(id), "r"(n) : "memory")

__device__ int g_mchc_ctr;

__global__ void mchc_reset(int start) { g_mchc_ctr = start; }

__device__ __forceinline__ float4 ld_cg4(const float* p) {
    return __ldcg(reinterpret_cast<const float4*>(p));
}

// butterfly step: values r[0..n-1] -> r[0..n/2-1]
#define BFLY_STEP(r, n, o)                                              \
    {                                                                   \
        const bool hi_ = (lane & (o)) != 0;                             \
        _Pragma("unroll")                                               \
        for (int v_ = 0; v_ < (n) / 2; v_++) {                          \
            float mine_  = hi_ ? r[v_ + (n) / 2] : r[v_];               \
            float other_ = hi_ ? r[v_] : r[v_ + (n) / 2];               \
            r[v_] = mine_ + __shfl_xor_sync(FULLM, other_, (o));        \
        }                                                               \
    }

__global__ void __launch_bounds__(THREADS, 1)
mchc_kernel(const float* __restrict__ x, const float* __restrict__ Wr,
            const float* __restrict__ br, float* __restrict__ out, int ntok)
{
    extern __shared__ float sm[];
    float* sWr  = sm;
    float* sP   = sm + SMEM_WR;
    float* sRaw = sP + SMEM_SP;      // 96 floats, raw index v = 4k + t
    float* sM   = sRaw + 96;         // 64 floats: sM[t*16 + i*4 + j]
    volatile int* sNext = (volatile int*)(sM + 64);

    const int tid  = threadIdx.x;
    const int lane = tid & 31;
    const int warp = tid >> 5;
    const int d0   = tid * 4;

    // stage W_router into smem once
    for (int i = tid * 4; i < SMEM_WR; i += THREADS * 4)
        *reinterpret_cast<float4*>(sWr + i) = *reinterpret_cast<const float4*>(Wr + i);
    __syncthreads();

    const int ngroups = (ntok + G - 1) / G;

    int g   = blockIdx.x;
    int gn1 = blockIdx.x + gridDim.x;    // lookahead-1 (deterministic seed)

    while (g < ngroups) {
        const int n0 = g * G;

        // ---- A: pass-1 read (L2-warm from prefetch) -> stream means ----
        float4 mx[G];
        #pragma unroll
        for (int t = 0; t < G; t++) {
            mx[t] = make_float4(0.f, 0.f, 0.f, 0.f);
            if (n0 + t < ntok) {
                const float* p = x + (size_t)(n0 + t) * (WS * DDIM) + d0;
                #pragma unroll
                for (int w = 0; w < WS; w++) {
                    float4 v = ld_cg4(p + w * DDIM);
                    mx[t].x += v.x; mx[t].y += v.y; mx[t].z += v.z; mx[t].w += v.w;
                }
                mx[t].x *= 0.25f; mx[t].y *= 0.25f; mx[t].z *= 0.25f; mx[t].w *= 0.25f;
            }
        }

        // ---- B: router partials, 3 sets of 32 values (v = 4k + t) ----
        float res0, res1, res2;
        #pragma unroll
        for (int set = 0; set < 3; set++) {
            float a[32];
            #pragma unroll
            for (int kk = 0; kk < 8; kk++) {
                const int k = 8 * set + kk;
                float4 wv = *reinterpret_cast<const float4*>(sWr + k * DDIM + d0);
                #pragma unroll
                for (int t = 0; t < G; t++)
                    a[kk * 4 + t] = wv.x * mx[t].x + wv.y * mx[t].y +
                                    wv.z * mx[t].z + wv.w * mx[t].w;
            }
            BFLY_STEP(a, 32, 16)
            BFLY_STEP(a, 16, 8)
            BFLY_STEP(a, 8, 4)
            BFLY_STEP(a, 4, 2)
            BFLY_STEP(a, 2, 1)
            if (set == 0) res0 = a[0];
            else if (set == 1) res1 = a[0];
            else res2 = a[0];
        }
        sP[warp * SP_STRIDE + lane]      = res0;
        sP[warp * SP_STRIDE + 32 + lane] = res1;
        sP[warp * SP_STRIDE + 64 + lane] = res2;

        if (warp >= 3) {
            // ============ WORKER (warps 3-15): never blocks at barA ============
            BAR_ARRIVE(1, THREADS);                 // publish sP

            // warm next group's x into L2 (gn1 grabbed last iteration)
            if (gn1 < ngroups) {
                const char* pb = reinterpret_cast<const char*>(
                                     x + (size_t)gn1 * G * (WS * DDIM)) + tid * 256;
                asm volatile("prefetch.global.L2 [%0];" :: "l"(pb));
                asm volatile("prefetch.global.L2 [%0];" :: "l"(pb + 128));
            }

            // F-phase loads issued BEFORE waiting on M (independent of M)
            float4 xf[G][WS];
            #pragma unroll
            for (int t = 0; t < G; t++) {
                const float* p = x + (size_t)(n0 + t) * (WS * DDIM) + d0;
                const bool ok = (n0 + t) < ntok;
                #pragma unroll
                for (int w = 0; w < WS; w++)
                    xf[t][w] = ok ? ld_cg4(p + w * DDIM) : make_float4(0,0,0,0);
            }

            BAR_SYNC(2, THREADS);                   // wait for M (hidden by loads)

            #pragma unroll
            for (int t = 0; t < G; t++) {
                if (n0 + t < ntok) {
                    float* o = out + (size_t)(n0 + t) * (WS * DDIM) + d0;
                    #pragma unroll
                    for (int i = 0; i < WS; i++) {
                        float4 Mi = *reinterpret_cast<const float4*>(sM + t * 16 + i * 4);
                        float4 ov;
                        ov.x = Mi.x*xf[t][0].x + Mi.y*xf[t][1].x + Mi.z*xf[t][2].x + Mi.w*xf[t][3].x;
                        ov.y = Mi.x*xf[t][0].y + Mi.y*xf[t][1].y + Mi.z*xf[t][2].y + Mi.w*xf[t][3].y;
                        ov.z = Mi.x*xf[t][0].z + Mi.y*xf[t][1].z + Mi.z*xf[t][2].z + Mi.w*xf[t][3].z;
                        ov.w = Mi.x*xf[t][0].w + Mi.y*xf[t][1].w + Mi.z*xf[t][2].w + Mi.w*xf[t][3].w;
                        __stcs(reinterpret_cast<float4*>(o + i * DDIM), ov);
                    }
                }
            }
        } else {
            // ============ ROUTER (warps 0-2) ============
            BAR_SYNC(1, THREADS);                   // barA: sP complete

            // steal the group-after-next; published via bar3 (w0-1) / barB (workers)
            if (warp == 2 && lane == 0)
                *sNext = atomicAdd(&g_mchc_ctr, 1);

            // reduce: warp w owns values v = 32w + lane (v = 4k + t)
            {
                float acc = __ldg(br + 8 * warp + (lane >> 2));
                #pragma unroll
                for (int w = 0; w < NW; w++)
                    acc += sP[w * SP_STRIDE + 32 * warp + lane];
                sRaw[32 * warp + lane] = acc;
            }
            BAR_SYNC(3, 96);                        // warps 0-2: sRaw complete

            if (warp < 2) {
                const int t = warp * 2 + (lane >> 4);   // token 0..3

                float p0 = sRaw[0*4+t], p1 = sRaw[1*4+t], p2 = sRaw[2*4+t], p3 = sRaw[3*4+t];
                float mp = fmaxf(fmaxf(p0, p1), fmaxf(p2, p3));
                p0 = __expf(p0 - mp); p1 = __expf(p1 - mp);
                p2 = __expf(p2 - mp); p3 = __expf(p3 - mp);
                float isp = __fdividef(1.f, p0 + p1 + p2 + p3);
                p0 *= isp; p1 *= isp; p2 *= isp; p3 *= isp;

                float q0 = sRaw[4*4+t], q1 = sRaw[5*4+t], q2 = sRaw[6*4+t], q3 = sRaw[7*4+t];
                float mq = fmaxf(fmaxf(q0, q1), fmaxf(q2, q3));
                q0 = __expf(q0 - mq); q1 = __expf(q1 - mq);
                q2 = __expf(q2 - mq); q3 = __expf(q3 - mq);
                float isq = __fdividef(1.f, q0 + q1 + q2 + q3);
                q0 *= isq; q1 *= isq; q2 *= isq; q3 *= isq;

                float av[16];
                #pragma unroll
                for (int i = 0; i < 4; i++)
                    #pragma unroll
                    for (int j = 0; j < 4; j++)
                        av[i*4+j] = __expf(sRaw[(8 + i*4 + j)*4 + t] + (i == j ? 2.0f : -2.0f));

                #pragma unroll
                for (int it = 0; it < 4; it++) {
                    #pragma unroll
                    for (int i = 0; i < 4; i++) {
                        float rs  = av[i*4] + av[i*4+1] + av[i*4+2] + av[i*4+3];
                        float inv = __fdividef(1.f, fmaxf(rs, EPSV));
                        av[i*4] *= inv; av[i*4+1] *= inv; av[i*4+2] *= inv; av[i*4+3] *= inv;
                    }
                    #pragma unroll
                    for (int j = 0; j < 4; j++) {
                        float cs  = av[j] + av[4+j] + av[8+j] + av[12+j];
                        float inv = __fdividef(1.f, fmaxf(cs, EPSV));
                        av[j] *= inv; av[4+j] *= inv; av[8+j] *= inv; av[12+j] *= inv;
                    }
                }

                if ((lane & 15) == 0) {
                    const float pre[4]  = {p0, p1, p2, p3};
                    const float post[4] = {q0, q1, q2, q3};
                    #pragma unroll
                    for (int i = 0; i < 4; i++) {
                        float4 mrow;
                        mrow.x = av[i*4+0] + post[i] * pre[0];
                        mrow.y = av[i*4+1] + post[i] * pre[1];
                        mrow.z = av[i*4+2] + post[i] * pre[2];
                        mrow.w = av[i*4+3] + post[i] * pre[3];
                        *reinterpret_cast<float4*>(sM + t * 16 + i * 4) = mrow;
                    }
                }
                BAR_SYNC(4, 64);                    // warps 0-1: full sM visible
                BAR_ARRIVE(2, THREADS);             // release barB
            } else {
                BAR_SYNC(2, THREADS);               // warp 2 waits for M
            }

            // prefetch share for warps 0-2 (gn1 grabbed last iteration)
            if (gn1 < ngroups) {
                const char* pb = reinterpret_cast<const char*>(
                                     x + (size_t)gn1 * G * (WS * DDIM)) + tid * 256;
                asm volatile("prefetch.global.L2 [%0];" :: "l"(pb));
                asm volatile("prefetch.global.L2 [%0];" :: "l"(pb + 128));
            }

            // F for warps 0-2 (loads after M; 3 of 16 warps, minor)
            #pragma unroll
            for (int t = 0; t < G; t++) {
                if (n0 + t < ntok) {
                    const float* p = x + (size_t)(n0 + t) * (WS * DDIM) + d0;
                    float*       o = out + (size_t)(n0 + t) * (WS * DDIM) + d0;
                    float4 x0 = ld_cg4(p);
                    float4 x1 = ld_cg4(p + DDIM);
                    float4 x2 = ld_cg4(p + 2 * DDIM);
                    float4 x3 = ld_cg4(p + 3 * DDIM);
                    #pragma unroll
                    for (int i = 0; i < WS; i++) {
                        float4 Mi = *reinterpret_cast<const float4*>(sM + t * 16 + i * 4);
                        float4 ov;
                        ov.x = Mi.x*x0.x + Mi.y*x1.x + Mi.z*x2.x + Mi.w*x3.x;
                        ov.y = Mi.x*x0.y + Mi.y*x1.y + Mi.z*x2.y + Mi.w*x3.y;
                        ov.z = Mi.x*x0.z + Mi.y*x1.z + Mi.z*x2.z + Mi.w*x3.z;
                        ov.w = Mi.x*x0.w + Mi.y*x1.w + Mi.z*x2.w + Mi.w*x3.w;
                        __stcs(reinterpret_cast<float4*>(o + i * DDIM), ov);
                    }
                }
            }
        }

        // advance: gn1 (grabbed last iter) becomes current; read this iter's
        // grab. Reads are ordered after the write by bar3 (warps 0-1) / barB
        // (everyone else); the NEXT write is gated behind barA(it+1)-sync,
        // which requires every thread to have passed this point.
        {
            int gn2 = *sNext;
            g = gn1;
            gn1 = gn2;
        }
    }
}

extern "C" void kernel_launch(void* const* d_in, const int* in_sizes, int n_in,
                              void* d_out, int out_size)
{
    const float* x  = (const float*)d_in[0];
    const float* Wr = (const float*)d_in[1];
    const float* br = (const float*)d_in[2];
    float* out = (float*)d_out;

    int ntok = in_sizes[0] / (WS * DDIM);   // 8192

    cudaFuncSetAttribute(mchc_kernel,
                         cudaFuncAttributeMaxDynamicSharedMemorySize, SMEM_BYTES);

    int sms = 148, dev = 0;
    if (cudaGetDevice(&dev) == cudaSuccess) {
        int v = 0;
        if (cudaDeviceGetAttribute(&v, cudaDevAttrMultiProcessorCount, dev) == cudaSuccess && v > 0)
            sms = v;
    }
    int ngroups = (ntok + G - 1) / G;
    int grid = (ngroups < sms) ? ngroups : sms;

    // counter starts at 2*grid: iteration 0 uses g=bid, gn1=bid+grid (static),
    // stealing covers groups >= 2*grid.
    mchc_reset<<<1, 1>>>(2 * grid);
    mchc_kernel<<<grid, THREADS, SMEM_BYTES>>>(x, Wr, br, out, ntok);
}

// round 17
// speedup vs baseline: 1.5479x; 1.0582x over previous
#include <cuda_runtime.h>
#include <cuda_bf16.h>

// ManifoldConstrainedHyperConnection — R12 (best: 121.3us) + half-register
// x reuse: tokens 0-1's stream values are kept in registers from the A phase
// through to the mix, eliminating their F-phase re-loads (8 LDG.128/thread/
// group = 512 wavefronts/CTA/group off the L1tex path). Tokens 2-3 keep
// R12's hoisted re-load pattern. Barriers/phases identical to R12:
//   barA (id1): warps 3-15 arrive, warps 0-2 sync
//   bar3 (id3, 96 thr): reduce handoff; bar4 (id4, 64 thr): sM visibility
//   barB (id2): warps 0-1 arrive after writing M; everyone else syncs,
//               workers with their F operands already in registers.

#define WRK 24
#define DDIM 2048
#define WS 4
#define THREADS 512
#define NW 16
#define G 4
#define EPSV 1e-6f

#define SMEM_WR (WRK * DDIM)            // 49152 floats (192 KB)
#define SP_STRIDE 100
#define SMEM_SP (NW * SP_STRIDE)        // 1600 floats
#define SMEM_FLOATS (SMEM_WR + SMEM_SP + 96 + 64)
#define SMEM_BYTES (SMEM_FLOATS * 4)

#define FULLM 0xffffffffu

// barriers: 1 = barA (512), 2 = barB (512), 3 = reduce-done (96), 4 = M-vis (64)
#define BAR_ARRIVE(id, n)  asm volatile("bar.arrive %0, %1;" :: "r"(id), "r"(n) : "memory")
#define BAR_SYNC(id, n)    asm volatile("bar.sync %0, %1;"   :: "r"(id), "r"(n) : "memory")

__device__ __forceinline__ float4 ld_cg4(const float* p) {
    return __ldcg(reinterpret_cast<const float4*>(p));
}

// butterfly step: values r[0..n-1] -> r[0..n/2-1]
#define BFLY_STEP(r, n, o)                                              \
    {                                                                   \
        const bool hi_ = (lane & (o)) != 0;                             \
        _Pragma("unroll")                                               \
        for (int v_ = 0; v_ < (n) / 2; v_++) {                          \
            float mine_  = hi_ ? r[v_ + (n) / 2] : r[v_];               \
            float other_ = hi_ ? r[v_] : r[v_ + (n) / 2];               \
            r[v_] = mine_ + __shfl_xor_sync(FULLM, other_, (o));        \
        }                                                               \
    }

// mix one token's 4-float slice from 4 stream float4s
#define MIX_STORE(o_ptr, Mbase, X0, X1, X2, X3)                         \
    {                                                                   \
        _Pragma("unroll")                                               \
        for (int i_ = 0; i_ < WS; i_++) {                               \
            float4 Mi_ = *reinterpret_cast<const float4*>((Mbase) + i_ * 4); \
            float4 ov_;                                                 \
            ov_.x = Mi_.x*(X0).x + Mi_.y*(X1).x + Mi_.z*(X2).x + Mi_.w*(X3).x; \
            ov_.y = Mi_.x*(X0).y + Mi_.y*(X1).y + Mi_.z*(X2).y + Mi_.w*(X3).y; \
            ov_.z = Mi_.x*(X0).z + Mi_.y*(X1).z + Mi_.z*(X2).z + Mi_.w*(X3).z; \
            ov_.w = Mi_.x*(X0).w + Mi_.y*(X1).w + Mi_.z*(X2).w + Mi_.w*(X3).w; \
            __stcs(reinterpret_cast<float4*>((o_ptr) + i_ * DDIM), ov_); \
        }                                                               \
    }

__global__ void __launch_bounds__(THREADS, 1)
mchc_kernel(const float* __restrict__ x, const float* __restrict__ Wr,
            const float* __restrict__ br, float* __restrict__ out, int ntok)
{
    extern __shared__ float sm[];
    float* sWr  = sm;
    float* sP   = sm + SMEM_WR;
    float* sRaw = sP + SMEM_SP;      // 96 floats, raw index v = 4k + t
    float* sM   = sRaw + 96;         // 64 floats: sM[t*16 + i*4 + j]

    const int tid  = threadIdx.x;
    const int lane = tid & 31;
    const int warp = tid >> 5;
    const int d0   = tid * 4;

    // stage W_router into smem once
    for (int i = tid * 4; i < SMEM_WR; i += THREADS * 4)
        *reinterpret_cast<float4*>(sWr + i) = *reinterpret_cast<const float4*>(Wr + i);
    __syncthreads();

    const int ngroups = (ntok + G - 1) / G;

    for (int g = blockIdx.x; g < ngroups; g += gridDim.x) {
        const int n0 = g * G;

        // ---- A: pass-1 read -> stream means; KEEP tokens 0-1 in registers ----
        float4 xv0[WS], xv1[WS];          // tokens 0 and 1 (reused in F)
        float4 mx[G];
        {
            const float* p0 = x + (size_t)(n0 + 0) * (WS * DDIM) + d0;
            const float* p1 = x + (size_t)(n0 + 1) * (WS * DDIM) + d0;
            const bool ok0 = (n0 + 0) < ntok, ok1 = (n0 + 1) < ntok;
            #pragma unroll
            for (int w = 0; w < WS; w++) {
                xv0[w] = ok0 ? ld_cg4(p0 + w * DDIM) : make_float4(0,0,0,0);
                xv1[w] = ok1 ? ld_cg4(p1 + w * DDIM) : make_float4(0,0,0,0);
            }
            mx[0].x = (xv0[0].x + xv0[1].x + xv0[2].x + xv0[3].x) * 0.25f;
            mx[0].y = (xv0[0].y + xv0[1].y + xv0[2].y + xv0[3].y) * 0.25f;
            mx[0].z = (xv0[0].z + xv0[1].z + xv0[2].z + xv0[3].z) * 0.25f;
            mx[0].w = (xv0[0].w + xv0[1].w + xv0[2].w + xv0[3].w) * 0.25f;
            mx[1].x = (xv1[0].x + xv1[1].x + xv1[2].x + xv1[3].x) * 0.25f;
            mx[1].y = (xv1[0].y + xv1[1].y + xv1[2].y + xv1[3].y) * 0.25f;
            mx[1].z = (xv1[0].z + xv1[1].z + xv1[2].z + xv1[3].z) * 0.25f;
            mx[1].w = (xv1[0].w + xv1[1].w + xv1[2].w + xv1[3].w) * 0.25f;
        }
        #pragma unroll
        for (int t = 2; t < G; t++) {
            mx[t] = make_float4(0.f, 0.f, 0.f, 0.f);
            if (n0 + t < ntok) {
                const float* p = x + (size_t)(n0 + t) * (WS * DDIM) + d0;
                #pragma unroll
                for (int w = 0; w < WS; w++) {
                    float4 v = ld_cg4(p + w * DDIM);
                    mx[t].x += v.x; mx[t].y += v.y; mx[t].z += v.z; mx[t].w += v.w;
                }
                mx[t].x *= 0.25f; mx[t].y *= 0.25f; mx[t].z *= 0.25f; mx[t].w *= 0.25f;
            }
        }

        // ---- B: router partials, 3 sets of 32 values (v = 4k + t) ----
        float res0, res1, res2;
        #pragma unroll
        for (int set = 0; set < 3; set++) {
            float a[32];
            #pragma unroll
            for (int kk = 0; kk < 8; kk++) {
                const int k = 8 * set + kk;
                float4 wv = *reinterpret_cast<const float4*>(sWr + k * DDIM + d0);
                #pragma unroll
                for (int t = 0; t < G; t++)
                    a[kk * 4 + t] = wv.x * mx[t].x + wv.y * mx[t].y +
                                    wv.z * mx[t].z + wv.w * mx[t].w;
            }
            BFLY_STEP(a, 32, 16)
            BFLY_STEP(a, 16, 8)
            BFLY_STEP(a, 8, 4)
            BFLY_STEP(a, 4, 2)
            BFLY_STEP(a, 2, 1)
            if (set == 0) res0 = a[0];
            else if (set == 1) res1 = a[0];
            else res2 = a[0];
        }
        sP[warp * SP_STRIDE + lane]      = res0;
        sP[warp * SP_STRIDE + 32 + lane] = res1;
        sP[warp * SP_STRIDE + 64 + lane] = res2;

        if (warp >= 3) {
            // ============ WORKER (warps 3-15): never blocks at barA ============
            BAR_ARRIVE(1, THREADS);                 // publish sP

            // warm next group's x into L2
            const int gn = g + gridDim.x;
            if (gn < ngroups) {
                const char* pb = reinterpret_cast<const char*>(
                                     x + (size_t)gn * G * (WS * DDIM)) + tid * 256;
                asm volatile("prefetch.global.L2 [%0];" :: "l"(pb));
                asm volatile("prefetch.global.L2 [%0];" :: "l"(pb + 128));
            }

            // hoist F-phase loads for tokens 2-3 only (0-1 already in regs)
            float4 xf2[2][WS];
            #pragma unroll
            for (int t = 0; t < 2; t++) {
                const float* p = x + (size_t)(n0 + 2 + t) * (WS * DDIM) + d0;
                const bool ok = (n0 + 2 + t) < ntok;
                #pragma unroll
                for (int w = 0; w < WS; w++)
                    xf2[t][w] = ok ? ld_cg4(p + w * DDIM) : make_float4(0,0,0,0);
            }

            BAR_SYNC(2, THREADS);                   // wait for M (hidden by loads)

            if (n0 + 0 < ntok) {
                float* o = out + (size_t)(n0 + 0) * (WS * DDIM) + d0;
                MIX_STORE(o, sM + 0 * 16, xv0[0], xv0[1], xv0[2], xv0[3]);
            }
            if (n0 + 1 < ntok) {
                float* o = out + (size_t)(n0 + 1) * (WS * DDIM) + d0;
                MIX_STORE(o, sM + 1 * 16, xv1[0], xv1[1], xv1[2], xv1[3]);
            }
            #pragma unroll
            for (int t = 0; t < 2; t++) {
                if (n0 + 2 + t < ntok) {
                    float* o = out + (size_t)(n0 + 2 + t) * (WS * DDIM) + d0;
                    MIX_STORE(o, sM + (2 + t) * 16,
                              xf2[t][0], xf2[t][1], xf2[t][2], xf2[t][3]);
                }
            }
        } else {
            // ============ ROUTER (warps 0-2) ============
            BAR_SYNC(1, THREADS);                   // barA: sP complete

            // reduce: warp w owns values v = 32w + lane (v = 4k + t)
            {
                float acc = __ldg(br + 8 * warp + (lane >> 2));
                #pragma unroll
                for (int w = 0; w < NW; w++)
                    acc += sP[w * SP_STRIDE + 32 * warp + lane];
                sRaw[32 * warp + lane] = acc;
            }
            BAR_SYNC(3, 96);                        // warps 0-2: sRaw complete

            if (warp < 2) {
                const int t = warp * 2 + (lane >> 4);   // token 0..3

                float p0 = sRaw[0*4+t], p1 = sRaw[1*4+t], p2 = sRaw[2*4+t], p3 = sRaw[3*4+t];
                float mp = fmaxf(fmaxf(p0, p1), fmaxf(p2, p3));
                p0 = __expf(p0 - mp); p1 = __expf(p1 - mp);
                p2 = __expf(p2 - mp); p3 = __expf(p3 - mp);
                float isp = __fdividef(1.f, p0 + p1 + p2 + p3);
                p0 *= isp; p1 *= isp; p2 *= isp; p3 *= isp;

                float q0 = sRaw[4*4+t], q1 = sRaw[5*4+t], q2 = sRaw[6*4+t], q3 = sRaw[7*4+t];
                float mq = fmaxf(fmaxf(q0, q1), fmaxf(q2, q3));
                q0 = __expf(q0 - mq); q1 = __expf(q1 - mq);
                q2 = __expf(q2 - mq); q3 = __expf(q3 - mq);
                float isq = __fdividef(1.f, q0 + q1 + q2 + q3);
                q0 *= isq; q1 *= isq; q2 *= isq; q3 *= isq;

                float av[16];
                #pragma unroll
                for (int i = 0; i < 4; i++)
                    #pragma unroll
                    for (int j = 0; j < 4; j++)
                        av[i*4+j] = __expf(sRaw[(8 + i*4 + j)*4 + t] + (i == j ? 2.0f : -2.0f));

                #pragma unroll
                for (int it = 0; it < 4; it++) {
                    #pragma unroll
                    for (int i = 0; i < 4; i++) {
                        float rs  = av[i*4] + av[i*4+1] + av[i*4+2] + av[i*4+3];
                        float inv = __fdividef(1.f, fmaxf(rs, EPSV));
                        av[i*4] *= inv; av[i*4+1] *= inv; av[i*4+2] *= inv; av[i*4+3] *= inv;
                    }
                    #pragma unroll
                    for (int j = 0; j < 4; j++) {
                        float cs  = av[j] + av[4+j] + av[8+j] + av[12+j];
                        float inv = __fdividef(1.f, fmaxf(cs, EPSV));
                        av[j] *= inv; av[4+j] *= inv; av[8+j] *= inv; av[12+j] *= inv;
                    }
                }

                if ((lane & 15) == 0) {
                    const float pre[4]  = {p0, p1, p2, p3};
                    const float post[4] = {q0, q1, q2, q3};
                    #pragma unroll
                    for (int i = 0; i < 4; i++) {
                        float4 mrow;
                        mrow.x = av[i*4+0] + post[i] * pre[0];
                        mrow.y = av[i*4+1] + post[i] * pre[1];
                        mrow.z = av[i*4+2] + post[i] * pre[2];
                        mrow.w = av[i*4+3] + post[i] * pre[3];
                        *reinterpret_cast<float4*>(sM + t * 16 + i * 4) = mrow;
                    }
                }
                BAR_SYNC(4, 64);                    // warps 0-1: full sM visible
                BAR_ARRIVE(2, THREADS);             // release barB
            } else {
                BAR_SYNC(2, THREADS);               // warp 2 waits for M
            }

            // prefetch share for warps 0-2
            const int gn = g + gridDim.x;
            if (gn < ngroups) {
                const char* pb = reinterpret_cast<const char*>(
                                     x + (size_t)gn * G * (WS * DDIM)) + tid * 256;
                asm volatile("prefetch.global.L2 [%0];" :: "l"(pb));
                asm volatile("prefetch.global.L2 [%0];" :: "l"(pb + 128));
            }

            // F: tokens 0-1 from registers (still live), 2-3 fresh L2 hits
            if (n0 + 0 < ntok) {
                float* o = out + (size_t)(n0 + 0) * (WS * DDIM) + d0;
                MIX_STORE(o, sM + 0 * 16, xv0[0], xv0[1], xv0[2], xv0[3]);
            }
            if (n0 + 1 < ntok) {
                float* o = out + (size_t)(n0 + 1) * (WS * DDIM) + d0;
                MIX_STORE(o, sM + 1 * 16, xv1[0], xv1[1], xv1[2], xv1[3]);
            }
            #pragma unroll
            for (int t = 2; t < G; t++) {
                if (n0 + t < ntok) {
                    const float* p = x + (size_t)(n0 + t) * (WS * DDIM) + d0;
                    float*       o = out + (size_t)(n0 + t) * (WS * DDIM) + d0;
                    float4 x0 = ld_cg4(p);
                    float4 x1 = ld_cg4(p + DDIM);
                    float4 x2 = ld_cg4(p + 2 * DDIM);
                    float4 x3 = ld_cg4(p + 3 * DDIM);
                    MIX_STORE(o, sM + t * 16, x0, x1, x2, x3);
                }
            }
        }
        // single-slot reuse ordering identical to R12:
        //   sP(it+1) written after barB(it) sync (program order)             ✓
        //   sM(it+1) written by warps 0-1 only after barA(it+1) sync, which
        //   requires all workers to have finished F(it) reads of sM          ✓
    }
}

extern "C" void kernel_launch(void* const* d_in, const int* in_sizes, int n_in,
                              void* d_out, int out_size)
{
    const float* x  = (const float*)d_in[0];
    const float* Wr = (const float*)d_in[1];
    const float* br = (const float*)d_in[2];
    float* out = (float*)d_out;

    int ntok = in_sizes[0] / (WS * DDIM);   // 8192

    cudaFuncSetAttribute(mchc_kernel,
                         cudaFuncAttributeMaxDynamicSharedMemorySize, SMEM_BYTES);

    int sms = 148, dev = 0;
    if (cudaGetDevice(&dev) == cudaSuccess) {
        int v = 0;
        if (cudaDeviceGetAttribute(&v, cudaDevAttrMultiProcessorCount, dev) == cudaSuccess && v > 0)
            sms = v;
    }
    int ngroups = (ntok + G - 1) / G;
    int grid = (ngroups < sms) ? ngroups : sms;

    mchc_kernel<<<grid, THREADS, SMEM_BYTES>>>(x, Wr, br, out, ntok);
}